// round 10
// baseline (speedup 1.0000x reference)
#include <cuda_runtime.h>
#include <cstdint>

// Problem constants
#define TT 512
#define BB 128
#define DD 256
#define HH 256

// ---- packed fp32x2 helpers (pre_gemm ONLY; measured regression in rnn) ----
#define FMA_F32X2(d, a, b, c) \
    asm("fma.rn.f32x2 %0, %1, %2, %3;" : "=l"(d) : "l"(a), "l"(b), "l"(c))
#define PACK_F32X2(out, lo, hi) \
    asm("mov.b64 %0, {%1, %2};" : "=l"(out) : "f"(lo), "f"(hi))
#define UNPACK_F32X2(lo, hi, in) \
    asm("mov.b64 {%0, %1}, %2;" : "=f"(lo), "=f"(hi) : "l"(in))

// =====================================================================
// Phase 1:  pre[t,b,j] = sum_d X[t,b,d] * Wi[j,d] + bh[j]
// (unchanged from R4/R5: measured ~145-190 us)
// =====================================================================
#define P1_BM 64
#define P1_BK 32
#define P1_BMP 66
#define P1_BNP 257

__global__ __launch_bounds__(256, 2)
void pre_gemm(const float* __restrict__ X, const float* __restrict__ Wi,
              const float* __restrict__ bh, float* __restrict__ out)
{
    __shared__ __align__(16) float As[P1_BK * P1_BMP];
    __shared__ __align__(16) float Bs[P1_BK * P1_BNP];

    const int tid = threadIdx.x;
    const int tx = tid & 31;
    const int ty = tid >> 5;
    const int row0 = blockIdx.x * P1_BM;

    uint64_t acc2[4][8];
#pragma unroll
    for (int r = 0; r < 4; r++)
#pragma unroll
        for (int c = 0; c < 8; c++) acc2[r][c] = 0ull;

    for (int k0 = 0; k0 < DD; k0 += P1_BK) {
#pragma unroll
        for (int i = 0; i < 2; i++) {
            int lin = i * 256 + tid;
            int m  = lin >> 3;
            int kq = lin & 7;
            float4 v = *(const float4*)(X + (row0 + m) * DD + k0 + kq * 4);
            As[(kq * 4 + 0) * P1_BMP + m] = v.x;
            As[(kq * 4 + 1) * P1_BMP + m] = v.y;
            As[(kq * 4 + 2) * P1_BMP + m] = v.z;
            As[(kq * 4 + 3) * P1_BMP + m] = v.w;
        }
#pragma unroll
        for (int i = 0; i < 8; i++) {
            int lin = i * 256 + tid;
            int n  = lin >> 3;
            int kq = lin & 7;
            float4 v = *(const float4*)(Wi + n * DD + k0 + kq * 4);
            Bs[(kq * 4 + 0) * P1_BNP + n] = v.x;
            Bs[(kq * 4 + 1) * P1_BNP + n] = v.y;
            Bs[(kq * 4 + 2) * P1_BNP + n] = v.z;
            Bs[(kq * 4 + 3) * P1_BNP + n] = v.w;
        }
        __syncthreads();

#pragma unroll 8
        for (int k = 0; k < P1_BK; k++) {
            const uint64_t* ap = (const uint64_t*)(As + k * P1_BMP + ty * 8);
            uint64_t a2[4];
            a2[0] = ap[0]; a2[1] = ap[1]; a2[2] = ap[2]; a2[3] = ap[3];
#pragma unroll
            for (int c = 0; c < 8; c++) {
                float bv = Bs[k * P1_BNP + c * 32 + tx];
                uint64_t bb;
                PACK_F32X2(bb, bv, bv);
#pragma unroll
                for (int r = 0; r < 4; r++)
                    FMA_F32X2(acc2[r][c], a2[r], bb, acc2[r][c]);
            }
        }
        __syncthreads();
    }

    float bias[8];
#pragma unroll
    for (int c = 0; c < 8; c++) bias[c] = bh[c * 32 + tx];
#pragma unroll
    for (int r = 0; r < 4; r++) {
        float* orow0 = out + (row0 + ty * 8 + 2 * r + 0) * HH;
        float* orow1 = out + (row0 + ty * 8 + 2 * r + 1) * HH;
#pragma unroll
        for (int c = 0; c < 8; c++) {
            float lo, hi;
            UNPACK_F32X2(lo, hi, acc2[r][c]);
            orow0[c * 32 + tx] = lo + bias[c];
            orow1[c * 32 + tx] = hi + bias[c];
        }
    }
}

// =====================================================================
// Phase 2: sequential recurrence, j-PAIR x k-QUARTER decomposition.
// One CTA per batch row b (128 CTAs), 512 threads = 16 warps.
//   tid: jp = tid >> 2 (0..127), kq = tid & 3 (0..3)
//   outputs j0 = 2*jp, j1 = 2*jp+1;  k range [kq*64, kq*64+64)
//   Per j: k-offsets 0..43 from registers (11 float4 x 2 j = 88 regs),
//          k-offsets 44..63 from smem (5 float4 x 2 j, conflict-free).
//   Each h float4 feeds BOTH j -> h-LDS halves to 16/thread; 8 acc chains.
//   Combine across 4 kq lanes: shfl_xor(1) + shfl_xor(2); kq==0 lane
//   stores float2 {hn0, hn1} to out and h_s.
// One __syncthreads per step. Scalar FFMA (f32x2 measured slower here).
// =====================================================================
#define P2_T    512
#define P2_KREG 44                       // per-j reg k-values
#define P2_KSM  20                       // per-j smem k-values
#define P2_PLANES (2 * (P2_KSM / 4))     // 10 planes of [512 threads][float4]
#define WHS_FLOATS (P2_PLANES * P2_T * 4)      // 20480 floats = 80KB
#define P2_SMEM_FLOATS (WHS_FLOATS + 2 * HH)
#define P2_SMEM_BYTES (P2_SMEM_FLOATS * (int)sizeof(float))

__global__ __launch_bounds__(P2_T, 1)
void rnn_seq(const float* __restrict__ Wh, const float* __restrict__ h0,
             float* __restrict__ out)
{
    extern __shared__ __align__(16) float sm[];
    float* Wh_s = sm;                       // [plane][tid][4]
    float* h_s  = sm + WHS_FLOATS;          // 2 x 256

    const int tid = threadIdx.x;
    const int kq  = tid & 3;
    const int jp  = tid >> 2;               // 0..127
    const int j0  = jp * 2;
    const int kbase = kq * 64;
    const bool owner = (kq == 0);
    const int b = blockIdx.x;

    // ---- register-resident weights ----
    float4 wr0[P2_KREG / 4], wr1[P2_KREG / 4];
#pragma unroll
    for (int i = 0; i < P2_KREG / 4; i++) {
        wr0[i] = *(const float4*)(Wh + (j0 + 0) * HH + kbase + i * 4);
        wr1[i] = *(const float4*)(Wh + (j0 + 1) * HH + kbase + i * 4);
    }

    // ---- smem-resident weights ----
    // plane p = 2*c + jsel; Wh_s[p*2048 + tt*4 + r] =
    //   Wh[2*(tt>>2)+jsel][(tt&3)*64 + P2_KREG + 4*c + r]
    for (int idx = tid; idx < P2_PLANES * P2_T * 4; idx += P2_T) {
        int p  = idx / (P2_T * 4);
        int r4 = idx - p * (P2_T * 4);
        int tt = r4 >> 2;
        int r  = r4 & 3;
        int c  = p >> 1;
        int jsel = p & 1;
        int jj = ((tt >> 2) << 1) + jsel;
        int kk = (tt & 3) * 64 + P2_KREG + 4 * c + r;
        Wh_s[p * (P2_T * 4) + tt * 4 + r] = Wh[jj * HH + kk];
    }
    if (tid < HH) h_s[tid] = h0[b * HH + tid];
    __syncthreads();

    const int obase = b * HH + j0;
    float2 pre2 = make_float2(0.0f, 0.0f);
    if (owner) pre2 = *(const float2*)(out + obase);   // pre[0]

    const float4* wsm = (const float4*)(Wh_s) + tid;   // + plane*512

    for (int t = 0; t < TT; t++) {
        float2 pre_next = make_float2(0.0f, 0.0f);
        if (owner && t + 1 < TT)
            pre_next = *(const float2*)(out + (t + 1) * (BB * HH) + obase);

        const float* hc = h_s + (t & 1) * HH + kbase;

        float a0[4] = {pre2.x, 0.0f, 0.0f, 0.0f};      // chains for j0
        float a1[4] = {pre2.y, 0.0f, 0.0f, 0.0f};      // chains for j1

        // k-offsets 0..43: register weights; each h4 feeds both j
#pragma unroll
        for (int c = 0; c < P2_KREG / 4; c++) {
            float4 h4 = *(const float4*)(hc + c * 4);
            a0[0] += h4.x * wr0[c].x;
            a0[1] += h4.y * wr0[c].y;
            a0[2] += h4.z * wr0[c].z;
            a0[3] += h4.w * wr0[c].w;
            a1[0] += h4.x * wr1[c].x;
            a1[1] += h4.y * wr1[c].y;
            a1[2] += h4.z * wr1[c].z;
            a1[3] += h4.w * wr1[c].w;
        }
        // k-offsets 44..63: smem weights, conflict-free LDS.128
#pragma unroll
        for (int c = 0; c < P2_KSM / 4; c++) {
            float4 h4 = *(const float4*)(hc + P2_KREG + c * 4);
            float4 w0 = wsm[(2 * c + 0) * P2_T];
            float4 w1 = wsm[(2 * c + 1) * P2_T];
            a0[0] += h4.x * w0.x;
            a0[1] += h4.y * w0.y;
            a0[2] += h4.z * w0.z;
            a0[3] += h4.w * w0.w;
            a1[0] += h4.x * w1.x;
            a1[1] += h4.y * w1.y;
            a1[2] += h4.z * w1.z;
            a1[3] += h4.w * w1.w;
        }

        float z0 = (a0[0] + a0[1]) + (a0[2] + a0[3]);
        float z1 = (a1[0] + a1[1]) + (a1[2] + a1[3]);

        // combine the 4 k-quarters (lanes differing in bits 0-1)
        z0 += __shfl_xor_sync(0xffffffffu, z0, 1);
        z0 += __shfl_xor_sync(0xffffffffu, z0, 2);
        z1 += __shfl_xor_sync(0xffffffffu, z1, 1);
        z1 += __shfl_xor_sync(0xffffffffu, z1, 2);

        float hn0 = __fdividef(1.0f, 1.0f + __expf(-z0));
        float hn1 = __fdividef(1.0f, 1.0f + __expf(-z1));

        if (owner) {
            *(float2*)(out + t * (BB * HH) + obase) = make_float2(hn0, hn1);
            *(float2*)(h_s + ((t + 1) & 1) * HH + j0) = make_float2(hn0, hn1);
        }
        __syncthreads();                     // h_s ready for step t+1
        pre2 = pre_next;
    }
}

// =====================================================================
// Launch
// Inputs: X [T,B,D], h [B,H], Wi [H,D], Wh [H,H], bh [H], many_to_many.
// =====================================================================
extern "C" void kernel_launch(void* const* d_in, const int* in_sizes, int n_in,
                              void* d_out, int out_size)
{
    const float* X  = (const float*)d_in[0];
    const float* h0 = (const float*)d_in[1];
    const float* Wi = (const float*)d_in[2];
    const float* Wh = (const float*)d_in[3];
    const float* bh = (const float*)d_in[4];
    float* out = (float*)d_out;

    pre_gemm<<<(TT * BB) / P1_BM, 256>>>(X, Wi, bh, out);

    cudaFuncSetAttribute(rnn_seq, cudaFuncAttributeMaxDynamicSharedMemorySize,
                         P2_SMEM_BYTES);
    rnn_seq<<<BB, P2_T, P2_SMEM_BYTES>>>(Wh, h0, out);
}

// round 12
// speedup vs baseline: 2.1713x; 2.1713x over previous
#include <cuda_runtime.h>
#include <cstdint>

// Problem constants
#define TT 512
#define BB 128
#define DD 256
#define HH 256

// ---- packed fp32x2 helpers (pre_gemm ONLY: measured -32% there, and
//      measured +27..30% REGRESSION in the latency-bound recurrence) ----
#define FMA_F32X2(d, a, b, c) \
    asm("fma.rn.f32x2 %0, %1, %2, %3;" : "=l"(d) : "l"(a), "l"(b), "l"(c))
#define PACK_F32X2(out, lo, hi) \
    asm("mov.b64 %0, {%1, %2};" : "=l"(out) : "f"(lo), "f"(hi))
#define UNPACK_F32X2(lo, hi, in) \
    asm("mov.b64 {%0, %1}, %2;" : "=f"(lo), "=f"(hi) : "l"(in))

// =====================================================================
// Phase 1:  pre[t,b,j] = sum_d X[t,b,d] * Wi[j,d] + bh[j]
// GEMM  M = 65536, N = 256, K = 256 -> d_out. f32x2-packed microtile.
// (unchanged from Round 4/5: measured ~145 us)
// =====================================================================
#define P1_BM 64
#define P1_BK 32
#define P1_BMP 66   // EVEN padded stride -> 8B-aligned LDS.64 a-pairs
#define P1_BNP 257  // padded stride for Bs

__global__ __launch_bounds__(256, 2)
void pre_gemm(const float* __restrict__ X, const float* __restrict__ Wi,
              const float* __restrict__ bh, float* __restrict__ out)
{
    __shared__ __align__(16) float As[P1_BK * P1_BMP];   // As[k][m]
    __shared__ __align__(16) float Bs[P1_BK * P1_BNP];   // Bs[k][n]

    const int tid = threadIdx.x;
    const int tx = tid & 31;
    const int ty = tid >> 5;
    const int row0 = blockIdx.x * P1_BM;

    uint64_t acc2[4][8];
#pragma unroll
    for (int r = 0; r < 4; r++)
#pragma unroll
        for (int c = 0; c < 8; c++) acc2[r][c] = 0ull;

    for (int k0 = 0; k0 < DD; k0 += P1_BK) {
#pragma unroll
        for (int i = 0; i < 2; i++) {
            int lin = i * 256 + tid;
            int m  = lin >> 3;
            int kq = lin & 7;
            float4 v = *(const float4*)(X + (row0 + m) * DD + k0 + kq * 4);
            As[(kq * 4 + 0) * P1_BMP + m] = v.x;
            As[(kq * 4 + 1) * P1_BMP + m] = v.y;
            As[(kq * 4 + 2) * P1_BMP + m] = v.z;
            As[(kq * 4 + 3) * P1_BMP + m] = v.w;
        }
#pragma unroll
        for (int i = 0; i < 8; i++) {
            int lin = i * 256 + tid;
            int n  = lin >> 3;
            int kq = lin & 7;
            float4 v = *(const float4*)(Wi + n * DD + k0 + kq * 4);
            Bs[(kq * 4 + 0) * P1_BNP + n] = v.x;
            Bs[(kq * 4 + 1) * P1_BNP + n] = v.y;
            Bs[(kq * 4 + 2) * P1_BNP + n] = v.z;
            Bs[(kq * 4 + 3) * P1_BNP + n] = v.w;
        }
        __syncthreads();

#pragma unroll 8
        for (int k = 0; k < P1_BK; k++) {
            const uint64_t* ap = (const uint64_t*)(As + k * P1_BMP + ty * 8);
            uint64_t a2[4];
            a2[0] = ap[0]; a2[1] = ap[1]; a2[2] = ap[2]; a2[3] = ap[3];
#pragma unroll
            for (int c = 0; c < 8; c++) {
                float bv = Bs[k * P1_BNP + c * 32 + tx];
                uint64_t bb;
                PACK_F32X2(bb, bv, bv);
#pragma unroll
                for (int r = 0; r < 4; r++)
                    FMA_F32X2(acc2[r][c], a2[r], bb, acc2[r][c]);
            }
        }
        __syncthreads();
    }

    float bias[8];
#pragma unroll
    for (int c = 0; c < 8; c++) bias[c] = bh[c * 32 + tx];
#pragma unroll
    for (int r = 0; r < 4; r++) {
        float* orow0 = out + (row0 + ty * 8 + 2 * r + 0) * HH;
        float* orow1 = out + (row0 + ty * 8 + 2 * r + 1) * HH;
#pragma unroll
        for (int c = 0; c < 8; c++) {
            float lo, hi;
            UNPACK_F32X2(lo, hi, acc2[r][c]);
            orow0[c * 32 + tx] = lo + bias[c];
            orow1[c * 32 + tx] = hi + bias[c];
        }
    }
}

// =====================================================================
// Phase 2: sequential recurrence, WARP-LOCAL k-split (shfl combine),
// with BANK-PADDED h buffer (the one change vs the 538us R8 kernel).
// One CTA per batch row b (128 CTAs), 512 threads = 16 warps.
//   warp w (0..15), lane l (0..31):
//     j     = w*16 + (l & 15)        (output index; 16 outputs per warp)
//     kbase = (l >> 4) * 128         (k half owned by this lane)
//   Wh[j][kbase+0 .. kbase+95]  -> 24 float4 registers
//   Wh[j][kbase+96.. kbase+127] -> smem, interleaved for conflict-free
//                                  LDS.128 at (float4*)Wh_s + tid + c*512
//   h -> smem double buffer; the two 128-float halves are stored at
//        stride H_PAD=132 floats (528B) so the per-warp pair of
//        broadcast addresses lands on DISJOINT banks (528/4 % 32 = 4)
//        -> each h LDS.128 is 1 wavefront instead of 2.
// Combine: s_total = s + shfl_xor(s, 16); one __syncthreads per step.
// Scalar FFMA throughout.
// =====================================================================
#define P2_T    512
#define P2_KREG 96                      // per-thread k-values in registers
#define P2_KSM  32                      // per-thread k-values in smem
#define WHS_FLOATS (8 * 2048)           // 8 c-groups x 512 thr x 4 = 64KB
#define H_PAD   132                     // padded half-stride (16B aligned, bank-shifted)
#define H_BUF   (2 * H_PAD)             // one phase: 264 floats
#define P2_SMEM_FLOATS (WHS_FLOATS + 2 * H_BUF)
#define P2_SMEM_BYTES (P2_SMEM_FLOATS * (int)sizeof(float))

__global__ __launch_bounds__(P2_T, 1)
void rnn_seq(const float* __restrict__ Wh, const float* __restrict__ h0,
             float* __restrict__ out)
{
    extern __shared__ __align__(16) float sm[];
    float* Wh_s = sm;                       // 16384 floats
    float* h_s  = sm + WHS_FLOATS;          // 2 phases x 264 floats

    const int tid  = threadIdx.x;
    const int l    = tid & 31;
    const int w    = tid >> 5;
    const int j    = w * 16 + (l & 15);     // output index
    const int khalf = l >> 4;               // 0 or 1
    const int kbase = khalf * 128;          // owned k half
    const bool lo_lane = (l < 16);
    const int b = blockIdx.x;

    // ---- register-resident weights: Wh[j][kbase .. kbase+95] ----
    float4 wr[P2_KREG / 4];
#pragma unroll
    for (int i = 0; i < P2_KREG / 4; i++)
        wr[i] = *(const float4*)(Wh + j * HH + kbase + i * 4);

    // ---- smem-resident weights (interleaved, conflict-free LDS.128) ----
    // Wh_s[(k>>2)*2048 + tt*4 + (k&3)] = Wh[j(tt)][kbase(tt)+96+k], k=0..31
    for (int idx = tid; idx < P2_T * P2_KSM; idx += P2_T) {
        int k  = idx & 31;
        int tt = idx >> 5;
        int jj = (tt >> 5) * 16 + (tt & 15);
        int kk = ((tt & 16) >> 4) * 128 + P2_KREG + k;
        Wh_s[(k >> 2) * 2048 + tt * 4 + (k & 3)] = Wh[jj * HH + kk];
    }
    // h init into the padded layout: h[k] -> h_s[(k>>7)*H_PAD + (k&127)]
    if (tid < HH)
        h_s[(tid >> 7) * H_PAD + (tid & 127)] = h0[b * HH + tid];
    __syncthreads();

    const int base = b * HH + j;
    float pre = lo_lane ? out[base] : 0.0f;   // pre[0] (low lanes carry it)

    const float4* wsm = (const float4*)(Wh_s) + tid;  // + c*512 per group
    const int h_store_off = (j >> 7) * H_PAD + (j & 127);

    for (int t = 0; t < TT; t++) {
        float pre_next = 0.0f;
        if (lo_lane && t + 1 < TT)
            pre_next = out[(t + 1) * (BB * HH) + base];

        const float* hc = h_s + (t & 1) * H_BUF + khalf * H_PAD;

        float a0 = pre, a1 = 0.0f, a2 = 0.0f, a3 = 0.0f;
        // k-offsets 0..95: register weights, h broadcast from smem
#pragma unroll
        for (int c = 0; c < P2_KREG / 4; c++) {
            float4 h4 = *(const float4*)(hc + c * 4);
            a0 += h4.x * wr[c].x;
            a1 += h4.y * wr[c].y;
            a2 += h4.z * wr[c].z;
            a3 += h4.w * wr[c].w;
        }
        // k-offsets 96..127: smem weights, conflict-free LDS.128
#pragma unroll
        for (int c = 0; c < P2_KSM / 4; c++) {
            float4 h4 = *(const float4*)(hc + P2_KREG + c * 4);
            float4 w4 = wsm[c * 512];
            a0 += h4.x * w4.x;
            a1 += h4.y * w4.y;
            a2 += h4.z * w4.z;
            a3 += h4.w * w4.w;
        }
        float s = (a0 + a1) + (a2 + a3);

        // combine k-halves within the warp: lane l <-> lane l^16
        s += __shfl_xor_sync(0xffffffffu, s, 16);

        float hn = __fdividef(1.0f, 1.0f + __expf(-s));
        if (lo_lane) {
            out[t * (BB * HH) + base] = hn;                    // result
            h_s[((t + 1) & 1) * H_BUF + h_store_off] = hn;     // next h
        }
        __syncthreads();                        // h_s ready for step t+1
        pre = pre_next;
    }
}

// =====================================================================
// Launch
// Inputs: X [T,B,D], h [B,H], Wi [H,D], Wh [H,H], bh [H], many_to_many.
// =====================================================================
extern "C" void kernel_launch(void* const* d_in, const int* in_sizes, int n_in,
                              void* d_out, int out_size)
{
    const float* X  = (const float*)d_in[0];
    const float* h0 = (const float*)d_in[1];
    const float* Wi = (const float*)d_in[2];
    const float* Wh = (const float*)d_in[3];
    const float* bh = (const float*)d_in[4];
    float* out = (float*)d_out;

    pre_gemm<<<(TT * BB) / P1_BM, 256>>>(X, Wi, bh, out);

    cudaFuncSetAttribute(rnn_seq, cudaFuncAttributeMaxDynamicSharedMemorySize,
                         P2_SMEM_BYTES);
    rnn_seq<<<BB, P2_T, P2_SMEM_BYTES>>>(Wh, h0, out);
}